// round 10
// baseline (speedup 1.0000x reference)
#include <cuda_runtime.h>
#include <cuda_fp16.h>
#include <stdint.h>

#define D_MODEL 1024
#define NUM_HEAD 16
#define HEAD_DIM 64
#define BATCH 2
#define SEQ 2048
#define MTOT 4096

// fp16 scratch
__device__ __half g_Q[(size_t)MTOT * D_MODEL];
__device__ __half g_K[(size_t)MTOT * D_MODEL];
__device__ __half g_VT[(size_t)BATCH * D_MODEL * SEQ];  // [b][d_global][token]
__device__ __half g_O[(size_t)MTOT * D_MODEL];
__device__ __half g_X[(size_t)MTOT * D_MODEL];
__device__ __half g_W[(size_t)4 * D_MODEL * D_MODEL];

__device__ __forceinline__ float ex2(float x) {
    float y;
    asm("ex2.approx.ftz.f32 %0, %1;" : "=f"(y) : "f"(x));
    return y;
}

__device__ __forceinline__ void mma_f16(float d[4], const uint32_t a[4],
                                        const uint32_t b[2], const float c[4]) {
    asm volatile(
        "mma.sync.aligned.m16n8k16.row.col.f32.f16.f16.f32 "
        "{%0,%1,%2,%3}, {%4,%5,%6,%7}, {%8,%9}, {%10,%11,%12,%13};\n"
        : "=f"(d[0]), "=f"(d[1]), "=f"(d[2]), "=f"(d[3])
        : "r"(a[0]), "r"(a[1]), "r"(a[2]), "r"(a[3]),
          "r"(b[0]), "r"(b[1]),
          "f"(c[0]), "f"(c[1]), "f"(c[2]), "f"(c[3]));
}

__device__ __forceinline__ uint32_t s2u(const void* p) {
    return (uint32_t)__cvta_generic_to_shared(p);
}
__device__ __forceinline__ void cp16(uint32_t s, const void* g) {
    asm volatile("cp.async.cg.shared.global [%0], [%1], 16;" :: "r"(s), "l"(g));
}
__device__ __forceinline__ void cpcommit() {
    asm volatile("cp.async.commit_group;");
}
template <int N> __device__ __forceinline__ void cpwait() {
    asm volatile("cp.async.wait_group %0;" :: "n"(N));
}

// ---------------------------------------------------------------------------
// Convert x and the 4 weight matrices to fp16 (rn).
// ---------------------------------------------------------------------------
__global__ __launch_bounds__(256) void preround(
    const float* __restrict__ x,
    const float* __restrict__ Wq, const float* __restrict__ Wk,
    const float* __restrict__ Wv, const float* __restrict__ Wo,
    __half* __restrict__ Xh, __half* __restrict__ Wh)
{
    const int bid = blockIdx.x;
    const float* src;
    __half* dst;
    size_t off;
    if (bid < 1024) {
        src = x; dst = Xh; off = (size_t)bid * 4096;
    } else {
        const int w = (bid - 1024) >> 8;
        const int lb = (bid - 1024) & 255;
        src = (w == 0) ? Wq : (w == 1) ? Wk : (w == 2) ? Wv : Wo;
        dst = Wh + (size_t)w * 1048576;
        off = (size_t)lb * 4096;
    }
    const float4* s4 = (const float4*)(src + off);
    __half2* d2 = (__half2*)(dst + off);
#pragma unroll
    for (int j = 0; j < 4; j++) {
        const int idx = threadIdx.x + j * 256;
        float4 v = s4[idx];
        d2[idx * 2] = __floats2half2_rn(v.x, v.y);
        d2[idx * 2 + 1] = __floats2half2_rn(v.z, v.w);
    }
}

// ---------------------------------------------------------------------------
// fp16 GEMM (NT): C[M,N] = A @ W^T + bias. 128x128x32 tiles, 4-stage cp.async,
// stage-unrolled immediate addressing. Smem rows: 32 halfs data + 16 pad
// (stride 48 halfs). m16n8k16 with logical-k remap (paired LDS.64 frags).
// Output modes: 0 = fp32, 1 = fp16 * qscale, 2 = fp16, 3 = fp16 transposed VT.
// ---------------------------------------------------------------------------
#define GROWH 48
#define GTH (128 * GROWH)    // 6144 halfs per operand tile
#define GSTGH (2 * GTH)      // 12288 halfs per stage
#define GSTGB (GSTGH * 2)    // 24576 bytes per stage

__global__ __launch_bounds__(256) void gemm_f16(
    const __half* __restrict__ A,
    const __half* __restrict__ W0, const __half* __restrict__ W1,
    const __half* __restrict__ W2,
    const float* __restrict__ b0p, const float* __restrict__ b1p,
    const float* __restrict__ b2p,
    void* __restrict__ C0, void* __restrict__ C1, void* __restrict__ C2,
    int m0_, int m1_, int m2_)
{
    extern __shared__ __half smh[];
    const int z = blockIdx.z;
    const __half* W = (z == 0) ? W0 : (z == 1) ? W1 : W2;
    const float* bias = (z == 0) ? b0p : (z == 1) ? b1p : b2p;
    void* C = (z == 0) ? C0 : (z == 1) ? C1 : C2;
    const int mode = (z == 0) ? m0_ : (z == 1) ? m1_ : m2_;
    const float oscale = (mode == 1) ? 0.18033688011112042f : 1.0f;

    const int tid = threadIdx.x;
    const int warp = tid >> 5, lane = tid & 31;
    const int wm = warp >> 1, wn = warp & 1;
    const int tm = lane >> 2, tk = lane & 3;

    const __half* Ab = A + (size_t)(blockIdx.y * 128) * D_MODEL;
    const __half* Wb = W + (size_t)(blockIdx.x * 128) * D_MODEL;

    const int lr = tid >> 1;         // 0..127
    const int lkh = (tid & 1) * 16;  // half offset 0 or 16

    const uint32_t sAb = s2u(smh + lr * GROWH + lkh);
    const uint32_t sBb = sAb + GTH * 2;
    const __half* gA = Ab + (size_t)lr * D_MODEL + lkh;
    const __half* gW = Wb + (size_t)lr * D_MODEL + lkh;

    const __half* pa0 = smh + (wm * 32 + tm) * GROWH + 4 * tk;
    const __half* pb0 = smh + GTH + (wn * 64 + tm) * GROWH + 4 * tk;

    float acc[2][8][4];
#pragma unroll
    for (int mt = 0; mt < 2; mt++)
#pragma unroll
        for (int nt = 0; nt < 8; nt++)
#pragma unroll
            for (int i = 0; i < 4; i++) acc[mt][nt][i] = 0.0f;

    // prologue: stages 0..2
#pragma unroll
    for (int s = 0; s < 3; s++) {
        cp16(sAb + s * GSTGB, gA + s * 32);
        cp16(sAb + s * GSTGB + 16, gA + s * 32 + 8);
        cp16(sBb + s * GSTGB, gW + s * 32);
        cp16(sBb + s * GSTGB + 16, gW + s * 32 + 8);
        cpcommit();
    }

#define GEMM_STAGE(SBUF, LBUF, KO, DOLOAD)                                    \
    {                                                                          \
        cpwait<2>();                                                           \
        __syncthreads();                                                       \
        if (DOLOAD) {                                                          \
            cp16(sAb + (LBUF) * GSTGB, gA + (KO));                             \
            cp16(sAb + (LBUF) * GSTGB + 16, gA + (KO) + 8);                    \
            cp16(sBb + (LBUF) * GSTGB, gW + (KO));                             \
            cp16(sBb + (LBUF) * GSTGB + 16, gW + (KO) + 8);                    \
        }                                                                      \
        cpcommit();                                                            \
        const __half* FA = pa0 + (SBUF) * GSTGH;                               \
        const __half* FB = pb0 + (SBUF) * GSTGH;                               \
        _Pragma("unroll")                                                      \
        for (int ks = 0; ks < 2; ks++) {                                       \
            uint32_t af[2][4], bf[8][2];                                       \
            {                                                                  \
                uint2 x0 = *(const uint2*)(FA + ks * 16);                      \
                uint2 y0 = *(const uint2*)(FA + 384 + ks * 16);                \
                af[0][0] = x0.x; af[0][1] = y0.x;                              \
                af[0][2] = x0.y; af[0][3] = y0.y;                              \
                uint2 x1 = *(const uint2*)(FA + 768 + ks * 16);                \
                uint2 y1 = *(const uint2*)(FA + 1152 + ks * 16);               \
                af[1][0] = x1.x; af[1][1] = y1.x;                              \
                af[1][2] = x1.y; af[1][3] = y1.y;                              \
            }                                                                  \
            _Pragma("unroll")                                                  \
            for (int nt = 0; nt < 8; nt++) {                                   \
                uint2 zv = *(const uint2*)(FB + nt * 384 + ks * 16);           \
                bf[nt][0] = zv.x; bf[nt][1] = zv.y;                            \
            }                                                                  \
            _Pragma("unroll")                                                  \
            for (int mt = 0; mt < 2; mt++)                                     \
                _Pragma("unroll")                                              \
                for (int nt = 0; nt < 8; nt++)                                 \
                    mma_f16(acc[mt][nt], af[mt], bf[nt], acc[mt][nt]);         \
        }                                                                      \
    }

    int koc = 96;  // stage 3 * 32 halfs
    for (int c = 0; c < 7; c++) {
        GEMM_STAGE(0, 3, koc, 1)
        GEMM_STAGE(1, 0, koc + 32, 1)
        GEMM_STAGE(2, 1, koc + 64, 1)
        GEMM_STAGE(3, 2, koc + 96, 1)
        koc += 128;
    }
    GEMM_STAGE(0, 3, koc, 1)   // stage 28, loads stage 31 (ko = 992)
    GEMM_STAGE(1, 0, 0, 0)
    GEMM_STAGE(2, 0, 0, 0)
    GEMM_STAGE(3, 0, 0, 0)
#undef GEMM_STAGE

    // ---- epilogue ----
#pragma unroll
    for (int mt = 0; mt < 2; mt++) {
        const int r0 = blockIdx.y * 128 + wm * 32 + mt * 16 + tm;
#pragma unroll
        for (int nt = 0; nt < 8; nt++) {
            const int col = blockIdx.x * 128 + wn * 64 + nt * 8 + 2 * tk;
            const float bb0 = bias[col], bb1 = bias[col + 1];
            float v0 = (acc[mt][nt][0] + bb0) * oscale;
            float v1 = (acc[mt][nt][1] + bb1) * oscale;
            float v2 = (acc[mt][nt][2] + bb0) * oscale;
            float v3 = (acc[mt][nt][3] + bb1) * oscale;
            if (mode == 0) {
                float* Cf = (float*)C;
                *(float2*)(Cf + (size_t)r0 * D_MODEL + col) = make_float2(v0, v1);
                *(float2*)(Cf + (size_t)(r0 + 8) * D_MODEL + col) =
                    make_float2(v2, v3);
            } else if (mode != 3) {
                __half* Ch = (__half*)C;
                *(__half2*)(Ch + (size_t)r0 * D_MODEL + col) =
                    __floats2half2_rn(v0, v1);
                *(__half2*)(Ch + (size_t)(r0 + 8) * D_MODEL + col) =
                    __floats2half2_rn(v2, v3);
            } else {
                // VT[b][col][token]
                const int bb = r0 >> 11;
                const int tok = r0 & 2047;
                __half* vb = (__half*)C + ((size_t)(bb * 1024 + col)) * 2048 + tok;
                vb[0] = __float2half_rn(v0);
                vb[2048] = __float2half_rn(v1);
                vb[8] = __float2half_rn(v2);
                vb[2048 + 8] = __float2half_rn(v3);
            }
        }
    }
}

// ---------------------------------------------------------------------------
// fp16 flash attention: 4 warps, BQ=64 (16 q-rows/warp), BKT=64, split-group
// cp.async K/VT, immediate addressing, m16n8k16 with 4-chunk logical-k remap.
// Smem halfs (stride 80/row): Qs[64] Ps[64] Ks[64] Vt[64] = 40960 B.
// 4 CTAs/SM -> finer wave granularity + cross-CTA phase overlap.
// ---------------------------------------------------------------------------
__global__ __launch_bounds__(128, 4) void flash_f16(
    const __half* __restrict__ Qg, const __half* __restrict__ Kg,
    const __half* __restrict__ VTg, __half* __restrict__ Og)
{
    extern __shared__ __half smh[];
    __half* Qs = smh;            // 64*80
    __half* Ps = smh + 5120;
    __half* Ks = smh + 10240;
    __half* Vt = smh + 15360;

    const int tid = threadIdx.x;
    const int warp = tid >> 5, lane = tid & 31;
    const int tm = lane >> 2, tk = lane & 3;
    const int b = blockIdx.y >> 4, h = blockIdx.y & 15;
    const int q0 = blockIdx.x * 64;

    const __half* Qb = Qg + (size_t)(b * SEQ + q0) * D_MODEL + h * HEAD_DIM;
    const __half* Kb = Kg + (size_t)(b * SEQ) * D_MODEL + h * HEAD_DIM;

    // ---- loader indices (128 threads): row = tid&63, half-col 0 or 32 ----
    const int ldr = tid & 63;
    const int ldc = (tid >> 6) * 32;

    // ---- Q tile via cp.async (group 1) ----
    {
        uint32_t sq = s2u(Qs + ldr * 80 + ldc);
        const __half* gq = Qb + (size_t)ldr * D_MODEL + ldc;
        cp16(sq, gq); cp16(sq + 16, gq + 8);
        cp16(sq + 32, gq + 16); cp16(sq + 48, gq + 24);
        cpcommit();
    }

    // ---- K/VT loaders: fixed addresses ----
    const uint32_t sK = s2u(Ks + ldr * 80 + ldc);
    const uint32_t sV = s2u(Vt + ldr * 80 + ldc);
    const __half* gK = Kb + (size_t)ldr * D_MODEL + ldc;
    const __half* gV = VTg + ((size_t)(b * 1024 + h * HEAD_DIM + ldr)) * 2048 + ldc;

    cp16(sK, gK); cp16(sK + 16, gK + 8);
    cp16(sK + 32, gK + 16); cp16(sK + 48, gK + 24);
    cpcommit();
    cp16(sV, gV); cp16(sV + 16, gV + 8);
    cp16(sV + 32, gV + 16); cp16(sV + 48, gV + 24);
    cpcommit();
    gK += 64 * D_MODEL;
    gV += 64;

    // ---- fragment base pointers ----
    const __half* pQ = Qs + (warp * 16 + tm) * 80 + 4 * tk;
    const __half* pP = Ps + (warp * 16 + tm) * 80 + 4 * tk;
    __half* pPst = Ps + (warp * 16 + tm) * 80 + 2 * tk;
    const __half* pK = Ks + tm * 80 + 4 * tk;
    const __half* pV = Vt + tm * 80 + 4 * tk;

    float s[8][4], acc[8][4], mi[2], li[2];
#pragma unroll
    for (int nt = 0; nt < 8; nt++)
#pragma unroll
        for (int i = 0; i < 4; i++) acc[nt][i] = 0.0f;
    mi[0] = mi[1] = -1e30f;
    li[0] = li[1] = 0.0f;

    const int NKT = SEQ / 64;  // 32

    for (int it = 0; it < NKT; it++) {
        cpwait<1>();          // Q + K(it) complete (VT group may be in flight)
        __syncthreads();

        // ---- S = Q @ K^T ----
#pragma unroll
        for (int nt = 0; nt < 8; nt++)
#pragma unroll
            for (int i = 0; i < 4; i++) s[nt][i] = 0.0f;

#pragma unroll
        for (int ks = 0; ks < 4; ks++) {
            uint32_t af[4], bf[8][2];
            uint2 x = *(const uint2*)(pQ + ks * 16);
            uint2 y = *(const uint2*)(pQ + 640 + ks * 16);
            af[0] = x.x; af[1] = y.x; af[2] = x.y; af[3] = y.y;
#pragma unroll
            for (int nt = 0; nt < 8; nt++) {
                uint2 zv = *(const uint2*)(pK + nt * 640 + ks * 16);
                bf[nt][0] = zv.x; bf[nt][1] = zv.y;
            }
#pragma unroll
            for (int nt = 0; nt < 8; nt++)
                mma_f16(s[nt], af, bf[nt], s[nt]);
        }

        __syncthreads();      // Ks reads done
        if (it + 1 < NKT) {   // K(it+1) overlaps softmax + PV
            cp16(sK, gK); cp16(sK + 16, gK + 8);
            cp16(sK + 32, gK + 16); cp16(sK + 48, gK + 24);
        }
        cpcommit();
        gK += 64 * D_MODEL;

        // ---- online softmax (log2 domain; scale folded into Q) ----
#pragma unroll
        for (int rh = 0; rh < 2; rh++) {
            float mx = -1e30f;
#pragma unroll
            for (int nt = 0; nt < 8; nt++)
#pragma unroll
                for (int j = 0; j < 2; j++)
                    mx = fmaxf(mx, s[nt][rh * 2 + j]);
            mx = fmaxf(mx, __shfl_xor_sync(0xffffffffu, mx, 1));
            mx = fmaxf(mx, __shfl_xor_sync(0xffffffffu, mx, 2));
            const float mn = fmaxf(mi[rh], mx);
            const float corr = ex2(mi[rh] - mn);
            mi[rh] = mn;
            float sum = 0.0f;
#pragma unroll
            for (int nt = 0; nt < 8; nt++)
#pragma unroll
                for (int j = 0; j < 2; j++) {
                    float p = ex2(s[nt][rh * 2 + j] - mn);
                    s[nt][rh * 2 + j] = p;
                    sum += p;
                }
            sum += __shfl_xor_sync(0xffffffffu, sum, 1);
            sum += __shfl_xor_sync(0xffffffffu, sum, 2);
            li[rh] = li[rh] * corr + sum;
#pragma unroll
            for (int nt = 0; nt < 8; nt++)
#pragma unroll
                for (int j = 0; j < 2; j++)
                    acc[nt][rh * 2 + j] *= corr;
        }

        // ---- P -> smem as fp16 (own rows; packed __half2 stores) ----
#pragma unroll
        for (int nt = 0; nt < 8; nt++)
#pragma unroll
            for (int rh = 0; rh < 2; rh++)
                *(__half2*)(pPst + rh * 640 + nt * 8) =
                    __floats2half2_rn(s[nt][rh * 2], s[nt][rh * 2 + 1]);
        __syncwarp();

        cpwait<1>();          // VT(it) complete (K(it+1) in flight)
        __syncthreads();

        // ---- O += P @ V  (B-frags from VT rows = d) ----
#pragma unroll
        for (int ks = 0; ks < 4; ks++) {
            uint32_t af[4], bf[8][2];
            uint2 x = *(const uint2*)(pP + ks * 16);
            uint2 y = *(const uint2*)(pP + 640 + ks * 16);
            af[0] = x.x; af[1] = y.x; af[2] = x.y; af[3] = y.y;
#pragma unroll
            for (int nt = 0; nt < 8; nt++) {
                uint2 zv = *(const uint2*)(pV + nt * 640 + ks * 16);
                bf[nt][0] = zv.x; bf[nt][1] = zv.y;
            }
#pragma unroll
            for (int nt = 0; nt < 8; nt++)
                mma_f16(acc[nt], af, bf[nt], acc[nt]);
        }

        __syncthreads();      // Vt reads done
        if (it + 1 < NKT) {   // VT(it+1) overlaps next S-MMA
            cp16(sV, gV); cp16(sV + 16, gV + 8);
            cp16(sV + 32, gV + 16); cp16(sV + 48, gV + 24);
        }
        cpcommit();
        gV += 64;
    }

    // ---- epilogue: normalize, fp16 out ----
#pragma unroll
    for (int rh = 0; rh < 2; rh++) {
        const float inv = 1.0f / li[rh];
        const int row = q0 + warp * 16 + tm + rh * 8;
        __half* orow = Og + (size_t)(b * SEQ + row) * D_MODEL + h * HEAD_DIM;
#pragma unroll
        for (int nt = 0; nt < 8; nt++) {
            const int col = nt * 8 + 2 * tk;
            *(__half2*)(orow + col) =
                __floats2half2_rn(acc[nt][rh * 2] * inv, acc[nt][rh * 2 + 1] * inv);
        }
    }
}

// ---------------------------------------------------------------------------
extern "C" void kernel_launch(void* const* d_in, const int* in_sizes, int n_in,
                              void* d_out, int out_size)
{
    const float* x  = (const float*)d_in[0];
    const float* Wq = (const float*)d_in[1];
    const float* bq = (const float*)d_in[2];
    const float* Wk = (const float*)d_in[3];
    const float* bk = (const float*)d_in[4];
    const float* Wv = (const float*)d_in[5];
    const float* bv = (const float*)d_in[6];
    const float* Wo = (const float*)d_in[7];
    const float* bo = (const float*)d_in[8];
    float* out = (float*)d_out;

    __half *Qd, *Kd, *VTd, *Od, *Xd, *Wd;
    cudaGetSymbolAddress((void**)&Qd, g_Q);
    cudaGetSymbolAddress((void**)&Kd, g_K);
    cudaGetSymbolAddress((void**)&VTd, g_VT);
    cudaGetSymbolAddress((void**)&Od, g_O);
    cudaGetSymbolAddress((void**)&Xd, g_X);
    cudaGetSymbolAddress((void**)&Wd, g_W);

    static int init = 0;
    if (!init) {
        cudaFuncSetAttribute(gemm_f16,
                             cudaFuncAttributeMaxDynamicSharedMemorySize, 98304);
        cudaFuncSetAttribute(flash_f16,
                             cudaFuncAttributeMaxDynamicSharedMemorySize, 40960);
        init = 1;
    }

    preround<<<2048, 256>>>(x, Wq, Wk, Wv, Wo, Xd, Wd);

    __half* Wqh = Wd;
    __half* Wkh = Wd + 1048576;
    __half* Wvh = Wd + 2097152;
    __half* Woh = Wd + 3145728;

    dim3 qkv_grid(D_MODEL / 128, MTOT / 128, 3);  // (8, 32, 3)
    gemm_f16<<<qkv_grid, 256, 98304>>>(Xd, Wqh, Wkh, Wvh, bq, bk, bv,
                                       Qd, Kd, VTd, 1, 2, 3);

    dim3 attn_grid(SEQ / 64, BATCH * NUM_HEAD);  // (32, 32)
    flash_f16<<<attn_grid, 128, 40960>>>(Qd, Kd, VTd, Od);

    dim3 o_grid(D_MODEL / 128, MTOT / 128, 1);    // (8, 32, 1)
    gemm_f16<<<o_grid, 256, 98304>>>(Od, Woh, Woh, Woh, bo, bo, bo,
                                     out, out, out, 0, 0, 0);
}

// round 11
// speedup vs baseline: 1.7418x; 1.7418x over previous
#include <cuda_runtime.h>
#include <cuda_fp16.h>
#include <stdint.h>

#define D_MODEL 1024
#define NUM_HEAD 16
#define HEAD_DIM 64
#define BATCH 2
#define SEQ 2048
#define MTOT 4096

// fp16 scratch
__device__ __half g_Q[(size_t)MTOT * D_MODEL];
__device__ __half g_K[(size_t)MTOT * D_MODEL];
__device__ __half g_VT[(size_t)BATCH * D_MODEL * SEQ];  // [b][d_global][token]
__device__ __half g_O[(size_t)MTOT * D_MODEL];
__device__ __half g_X[(size_t)MTOT * D_MODEL];
__device__ __half g_W[(size_t)4 * D_MODEL * D_MODEL];

__device__ __forceinline__ float ex2(float x) {
    float y;
    asm("ex2.approx.ftz.f32 %0, %1;" : "=f"(y) : "f"(x));
    return y;
}
// packed fp16x2 exp2: one MUFU op for two values
__device__ __forceinline__ uint32_t ex2_h2(uint32_t x) {
    uint32_t y;
    asm("ex2.approx.f16x2 %0, %1;" : "=r"(y) : "r"(x));
    return y;
}

__device__ __forceinline__ void mma_f16(float d[4], const uint32_t a[4],
                                        const uint32_t b[2], const float c[4]) {
    asm volatile(
        "mma.sync.aligned.m16n8k16.row.col.f32.f16.f16.f32 "
        "{%0,%1,%2,%3}, {%4,%5,%6,%7}, {%8,%9}, {%10,%11,%12,%13};\n"
        : "=f"(d[0]), "=f"(d[1]), "=f"(d[2]), "=f"(d[3])
        : "r"(a[0]), "r"(a[1]), "r"(a[2]), "r"(a[3]),
          "r"(b[0]), "r"(b[1]),
          "f"(c[0]), "f"(c[1]), "f"(c[2]), "f"(c[3]));
}

__device__ __forceinline__ uint32_t s2u(const void* p) {
    return (uint32_t)__cvta_generic_to_shared(p);
}
__device__ __forceinline__ void cp16(uint32_t s, const void* g) {
    asm volatile("cp.async.cg.shared.global [%0], [%1], 16;" :: "r"(s), "l"(g));
}
__device__ __forceinline__ void cpcommit() {
    asm volatile("cp.async.commit_group;");
}
template <int N> __device__ __forceinline__ void cpwait() {
    asm volatile("cp.async.wait_group %0;" :: "n"(N));
}

// ---------------------------------------------------------------------------
// Convert x and the 4 weight matrices to fp16 (rn).
// ---------------------------------------------------------------------------
__global__ __launch_bounds__(256) void preround(
    const float* __restrict__ x,
    const float* __restrict__ Wq, const float* __restrict__ Wk,
    const float* __restrict__ Wv, const float* __restrict__ Wo,
    __half* __restrict__ Xh, __half* __restrict__ Wh)
{
    const int bid = blockIdx.x;
    const float* src;
    __half* dst;
    size_t off;
    if (bid < 1024) {
        src = x; dst = Xh; off = (size_t)bid * 4096;
    } else {
        const int w = (bid - 1024) >> 8;
        const int lb = (bid - 1024) & 255;
        src = (w == 0) ? Wq : (w == 1) ? Wk : (w == 2) ? Wv : Wo;
        dst = Wh + (size_t)w * 1048576;
        off = (size_t)lb * 4096;
    }
    const float4* s4 = (const float4*)(src + off);
    __half2* d2 = (__half2*)(dst + off);
#pragma unroll
    for (int j = 0; j < 4; j++) {
        const int idx = threadIdx.x + j * 256;
        float4 v = s4[idx];
        d2[idx * 2] = __floats2half2_rn(v.x, v.y);
        d2[idx * 2 + 1] = __floats2half2_rn(v.z, v.w);
    }
}

// ---------------------------------------------------------------------------
// fp16 GEMM (NT): C[M,N] = A @ W^T + bias. 128x128x32 tiles, 4-stage cp.async,
// stage-unrolled immediate addressing. Smem rows: 32 halfs data + 16 pad
// (stride 48 halfs). m16n8k16 with logical-k remap (paired LDS.64 frags).
// Output modes: 0 = fp32, 1 = fp16 * qscale, 2 = fp16, 3 = fp16 transposed VT.
// ---------------------------------------------------------------------------
#define GROWH 48
#define GTH (128 * GROWH)    // 6144 halfs per operand tile
#define GSTGH (2 * GTH)      // 12288 halfs per stage
#define GSTGB (GSTGH * 2)    // 24576 bytes per stage

__global__ __launch_bounds__(256) void gemm_f16(
    const __half* __restrict__ A,
    const __half* __restrict__ W0, const __half* __restrict__ W1,
    const __half* __restrict__ W2,
    const float* __restrict__ b0p, const float* __restrict__ b1p,
    const float* __restrict__ b2p,
    void* __restrict__ C0, void* __restrict__ C1, void* __restrict__ C2,
    int m0_, int m1_, int m2_)
{
    extern __shared__ __half smh[];
    const int z = blockIdx.z;
    const __half* W = (z == 0) ? W0 : (z == 1) ? W1 : W2;
    const float* bias = (z == 0) ? b0p : (z == 1) ? b1p : b2p;
    void* C = (z == 0) ? C0 : (z == 1) ? C1 : C2;
    const int mode = (z == 0) ? m0_ : (z == 1) ? m1_ : m2_;
    const float oscale = (mode == 1) ? 0.18033688011112042f : 1.0f;

    const int tid = threadIdx.x;
    const int warp = tid >> 5, lane = tid & 31;
    const int wm = warp >> 1, wn = warp & 1;
    const int tm = lane >> 2, tk = lane & 3;

    const __half* Ab = A + (size_t)(blockIdx.y * 128) * D_MODEL;
    const __half* Wb = W + (size_t)(blockIdx.x * 128) * D_MODEL;

    const int lr = tid >> 1;         // 0..127
    const int lkh = (tid & 1) * 16;  // half offset 0 or 16

    const uint32_t sAb = s2u(smh + lr * GROWH + lkh);
    const uint32_t sBb = sAb + GTH * 2;
    const __half* gA = Ab + (size_t)lr * D_MODEL + lkh;
    const __half* gW = Wb + (size_t)lr * D_MODEL + lkh;

    const __half* pa0 = smh + (wm * 32 + tm) * GROWH + 4 * tk;
    const __half* pb0 = smh + GTH + (wn * 64 + tm) * GROWH + 4 * tk;

    float acc[2][8][4];
#pragma unroll
    for (int mt = 0; mt < 2; mt++)
#pragma unroll
        for (int nt = 0; nt < 8; nt++)
#pragma unroll
            for (int i = 0; i < 4; i++) acc[mt][nt][i] = 0.0f;

    // prologue: stages 0..2
#pragma unroll
    for (int s = 0; s < 3; s++) {
        cp16(sAb + s * GSTGB, gA + s * 32);
        cp16(sAb + s * GSTGB + 16, gA + s * 32 + 8);
        cp16(sBb + s * GSTGB, gW + s * 32);
        cp16(sBb + s * GSTGB + 16, gW + s * 32 + 8);
        cpcommit();
    }

#define GEMM_STAGE(SBUF, LBUF, KO, DOLOAD)                                    \
    {                                                                          \
        cpwait<2>();                                                           \
        __syncthreads();                                                       \
        if (DOLOAD) {                                                          \
            cp16(sAb + (LBUF) * GSTGB, gA + (KO));                             \
            cp16(sAb + (LBUF) * GSTGB + 16, gA + (KO) + 8);                    \
            cp16(sBb + (LBUF) * GSTGB, gW + (KO));                             \
            cp16(sBb + (LBUF) * GSTGB + 16, gW + (KO) + 8);                    \
        }                                                                      \
        cpcommit();                                                            \
        const __half* FA = pa0 + (SBUF) * GSTGH;                               \
        const __half* FB = pb0 + (SBUF) * GSTGH;                               \
        _Pragma("unroll")                                                      \
        for (int ks = 0; ks < 2; ks++) {                                       \
            uint32_t af[2][4], bf[8][2];                                       \
            {                                                                  \
                uint2 x0 = *(const uint2*)(FA + ks * 16);                      \
                uint2 y0 = *(const uint2*)(FA + 384 + ks * 16);                \
                af[0][0] = x0.x; af[0][1] = y0.x;                              \
                af[0][2] = x0.y; af[0][3] = y0.y;                              \
                uint2 x1 = *(const uint2*)(FA + 768 + ks * 16);                \
                uint2 y1 = *(const uint2*)(FA + 1152 + ks * 16);               \
                af[1][0] = x1.x; af[1][1] = y1.x;                              \
                af[1][2] = x1.y; af[1][3] = y1.y;                              \
            }                                                                  \
            _Pragma("unroll")                                                  \
            for (int nt = 0; nt < 8; nt++) {                                   \
                uint2 zv = *(const uint2*)(FB + nt * 384 + ks * 16);           \
                bf[nt][0] = zv.x; bf[nt][1] = zv.y;                            \
            }                                                                  \
            _Pragma("unroll")                                                  \
            for (int mt = 0; mt < 2; mt++)                                     \
                _Pragma("unroll")                                              \
                for (int nt = 0; nt < 8; nt++)                                 \
                    mma_f16(acc[mt][nt], af[mt], bf[nt], acc[mt][nt]);         \
        }                                                                      \
    }

    int koc = 96;  // stage 3 * 32 halfs
    for (int c = 0; c < 7; c++) {
        GEMM_STAGE(0, 3, koc, 1)
        GEMM_STAGE(1, 0, koc + 32, 1)
        GEMM_STAGE(2, 1, koc + 64, 1)
        GEMM_STAGE(3, 2, koc + 96, 1)
        koc += 128;
    }
    GEMM_STAGE(0, 3, koc, 1)   // stage 28, loads stage 31 (ko = 992)
    GEMM_STAGE(1, 0, 0, 0)
    GEMM_STAGE(2, 0, 0, 0)
    GEMM_STAGE(3, 0, 0, 0)
#undef GEMM_STAGE

    // ---- epilogue ----
#pragma unroll
    for (int mt = 0; mt < 2; mt++) {
        const int r0 = blockIdx.y * 128 + wm * 32 + mt * 16 + tm;
#pragma unroll
        for (int nt = 0; nt < 8; nt++) {
            const int col = blockIdx.x * 128 + wn * 64 + nt * 8 + 2 * tk;
            const float bb0 = bias[col], bb1 = bias[col + 1];
            float v0 = (acc[mt][nt][0] + bb0) * oscale;
            float v1 = (acc[mt][nt][1] + bb1) * oscale;
            float v2 = (acc[mt][nt][2] + bb0) * oscale;
            float v3 = (acc[mt][nt][3] + bb1) * oscale;
            if (mode == 0) {
                float* Cf = (float*)C;
                *(float2*)(Cf + (size_t)r0 * D_MODEL + col) = make_float2(v0, v1);
                *(float2*)(Cf + (size_t)(r0 + 8) * D_MODEL + col) =
                    make_float2(v2, v3);
            } else if (mode != 3) {
                __half* Ch = (__half*)C;
                *(__half2*)(Ch + (size_t)r0 * D_MODEL + col) =
                    __floats2half2_rn(v0, v1);
                *(__half2*)(Ch + (size_t)(r0 + 8) * D_MODEL + col) =
                    __floats2half2_rn(v2, v3);
            } else {
                // VT[b][col][token]
                const int bb = r0 >> 11;
                const int tok = r0 & 2047;
                __half* vb = (__half*)C + ((size_t)(bb * 1024 + col)) * 2048 + tok;
                vb[0] = __float2half_rn(v0);
                vb[2048] = __float2half_rn(v1);
                vb[8] = __float2half_rn(v2);
                vb[2048 + 8] = __float2half_rn(v3);
            }
        }
    }
}

// ---------------------------------------------------------------------------
// fp16 flash attention (R9 shape): 8 warps, BQ=128 (16 q-rows/warp), BKT=64,
// split-group cp.async K/VT, immediate addressing, m16n8k16 logical-k remap.
// NEW: softmax exponentials via ex2.approx.f16x2 (half the MUFU ops); P is
// produced directly in fp16 and stored inside the softmax loop.
// Smem halfs (stride 80/row): Qs[128] Ps[128] Ks[64] Vt[64] = 61440 B.
// ---------------------------------------------------------------------------
__global__ __launch_bounds__(256, 2) void flash_f16(
    const __half* __restrict__ Qg, const __half* __restrict__ Kg,
    const __half* __restrict__ VTg, __half* __restrict__ Og)
{
    extern __shared__ __half smh[];
    __half* Qs = smh;            // 128*80
    __half* Ps = smh + 10240;
    __half* Ks = smh + 20480;    // 64*80
    __half* Vt = smh + 25600;

    const int tid = threadIdx.x;
    const int warp = tid >> 5, lane = tid & 31;
    const int tm = lane >> 2, tk = lane & 3;
    const int b = blockIdx.y >> 4, h = blockIdx.y & 15;
    const int q0 = blockIdx.x * 128;

    const __half* Qb = Qg + (size_t)(b * SEQ + q0) * D_MODEL + h * HEAD_DIM;
    const __half* Kb = Kg + (size_t)(b * SEQ) * D_MODEL + h * HEAD_DIM;

    // ---- Q tile via cp.async (group 1) ----
    {
        const int qr = tid >> 1;
        const int qc = (tid & 1) * 32;
        uint32_t sq = s2u(Qs + qr * 80 + qc);
        const __half* gq = Qb + (size_t)qr * D_MODEL + qc;
        cp16(sq, gq); cp16(sq + 16, gq + 8);
        cp16(sq + 32, gq + 16); cp16(sq + 48, gq + 24);
        cpcommit();
    }

    // ---- K/VT loaders: fixed addresses ----
    const int kr = tid >> 2;
    const int kc = (tid & 3) * 16;
    const uint32_t sK = s2u(Ks + kr * 80 + kc);
    const uint32_t sV = s2u(Vt + kr * 80 + kc);
    const __half* gK = Kb + (size_t)kr * D_MODEL + kc;
    const __half* gV = VTg + ((size_t)(b * 1024 + h * HEAD_DIM + kr)) * 2048 + kc;

    cp16(sK, gK); cp16(sK + 16, gK + 8);
    cpcommit();
    cp16(sV, gV); cp16(sV + 16, gV + 8);
    cpcommit();
    gK += 64 * D_MODEL;
    gV += 64;

    // ---- fragment base pointers ----
    const __half* pQ = Qs + (warp * 16 + tm) * 80 + 4 * tk;
    const __half* pP = Ps + (warp * 16 + tm) * 80 + 4 * tk;
    __half* pPst = Ps + (warp * 16 + tm) * 80 + 2 * tk;
    const __half* pK = Ks + tm * 80 + 4 * tk;
    const __half* pV = Vt + tm * 80 + 4 * tk;

    float s[8][4], acc[8][4], mi[2], li[2];
#pragma unroll
    for (int nt = 0; nt < 8; nt++)
#pragma unroll
        for (int i = 0; i < 4; i++) acc[nt][i] = 0.0f;
    mi[0] = mi[1] = -1e30f;
    li[0] = li[1] = 0.0f;

    const int NKT = SEQ / 64;  // 32

    for (int it = 0; it < NKT; it++) {
        cpwait<1>();          // Q + K(it) complete (VT group may be in flight)
        __syncthreads();

        // ---- S = Q @ K^T ----
#pragma unroll
        for (int nt = 0; nt < 8; nt++)
#pragma unroll
            for (int i = 0; i < 4; i++) s[nt][i] = 0.0f;

#pragma unroll
        for (int ks = 0; ks < 4; ks++) {
            uint32_t af[4], bf[8][2];
            uint2 x = *(const uint2*)(pQ + ks * 16);
            uint2 y = *(const uint2*)(pQ + 640 + ks * 16);
            af[0] = x.x; af[1] = y.x; af[2] = x.y; af[3] = y.y;
#pragma unroll
            for (int nt = 0; nt < 8; nt++) {
                uint2 zv = *(const uint2*)(pK + nt * 640 + ks * 16);
                bf[nt][0] = zv.x; bf[nt][1] = zv.y;
            }
#pragma unroll
            for (int nt = 0; nt < 8; nt++)
                mma_f16(s[nt], af, bf[nt], s[nt]);
        }

        __syncthreads();      // Ks reads done
        if (it + 1 < NKT) {   // K(it+1) overlaps softmax + PV
            cp16(sK, gK); cp16(sK + 16, gK + 8);
        }
        cpcommit();
        gK += 64 * D_MODEL;

        // ---- online softmax (log2 domain; scale folded into Q) ----
        // exp in packed fp16x2 (half the MUFU ops); P stored directly.
#pragma unroll
        for (int rh = 0; rh < 2; rh++) {
            float mx = -1e30f;
#pragma unroll
            for (int nt = 0; nt < 8; nt++)
#pragma unroll
                for (int j = 0; j < 2; j++)
                    mx = fmaxf(mx, s[nt][rh * 2 + j]);
            mx = fmaxf(mx, __shfl_xor_sync(0xffffffffu, mx, 1));
            mx = fmaxf(mx, __shfl_xor_sync(0xffffffffu, mx, 2));
            const float mn = fmaxf(mi[rh], mx);
            const float corr = ex2(mi[rh] - mn);
            mi[rh] = mn;
            float sum = 0.0f;
#pragma unroll
            for (int nt = 0; nt < 8; nt++) {
                __half2 t = __floats2half2_rn(s[nt][rh * 2] - mn,
                                              s[nt][rh * 2 + 1] - mn);
                uint32_t p2 = ex2_h2(*(uint32_t*)&t);
                *(uint32_t*)(pPst + rh * 640 + nt * 8) = p2;   // P -> smem (fp16)
                __half2 ph = *(__half2*)&p2;
                sum += __low2float(ph) + __high2float(ph);
            }
            sum += __shfl_xor_sync(0xffffffffu, sum, 1);
            sum += __shfl_xor_sync(0xffffffffu, sum, 2);
            li[rh] = li[rh] * corr + sum;
#pragma unroll
            for (int nt = 0; nt < 8; nt++)
#pragma unroll
                for (int j = 0; j < 2; j++)
                    acc[nt][rh * 2 + j] *= corr;
        }
        __syncwarp();

        cpwait<1>();          // VT(it) complete (K(it+1) in flight)
        __syncthreads();

        // ---- O += P @ V  (B-frags from VT rows = d) ----
#pragma unroll
        for (int ks = 0; ks < 4; ks++) {
            uint32_t af[4], bf[8][2];
            uint2 x = *(const uint2*)(pP + ks * 16);
            uint2 y = *(const uint2*)(pP + 640 + ks * 16);
            af[0] = x.x; af[1] = y.x; af[2] = x.y; af[3] = y.y;
#pragma unroll
            for (int nt = 0; nt < 8; nt++) {
                uint2 zv = *(const uint2*)(pV + nt * 640 + ks * 16);
                bf[nt][0] = zv.x; bf[nt][1] = zv.y;
            }
#pragma unroll
            for (int nt = 0; nt < 8; nt++)
                mma_f16(acc[nt], af, bf[nt], acc[nt]);
        }

        __syncthreads();      // Vt reads done
        if (it + 1 < NKT) {   // VT(it+1) overlaps next S-MMA
            cp16(sV, gV); cp16(sV + 16, gV + 8);
        }
        cpcommit();
        gV += 64;
    }

    // ---- epilogue: normalize, fp16 out ----
#pragma unroll
    for (int rh = 0; rh < 2; rh++) {
        const float inv = 1.0f / li[rh];
        const int row = q0 + warp * 16 + tm + rh * 8;
        __half* orow = Og + (size_t)(b * SEQ + row) * D_MODEL + h * HEAD_DIM;
#pragma unroll
        for (int nt = 0; nt < 8; nt++) {
            const int col = nt * 8 + 2 * tk;
            *(__half2*)(orow + col) =
                __floats2half2_rn(acc[nt][rh * 2] * inv, acc[nt][rh * 2 + 1] * inv);
        }
    }
}

// ---------------------------------------------------------------------------
extern "C" void kernel_launch(void* const* d_in, const int* in_sizes, int n_in,
                              void* d_out, int out_size)
{
    const float* x  = (const float*)d_in[0];
    const float* Wq = (const float*)d_in[1];
    const float* bq = (const float*)d_in[2];
    const float* Wk = (const float*)d_in[3];
    const float* bk = (const float*)d_in[4];
    const float* Wv = (const float*)d_in[5];
    const float* bv = (const float*)d_in[6];
    const float* Wo = (const float*)d_in[7];
    const float* bo = (const float*)d_in[8];
    float* out = (float*)d_out;

    __half *Qd, *Kd, *VTd, *Od, *Xd, *Wd;
    cudaGetSymbolAddress((void**)&Qd, g_Q);
    cudaGetSymbolAddress((void**)&Kd, g_K);
    cudaGetSymbolAddress((void**)&VTd, g_VT);
    cudaGetSymbolAddress((void**)&Od, g_O);
    cudaGetSymbolAddress((void**)&Xd, g_X);
    cudaGetSymbolAddress((void**)&Wd, g_W);

    static int init = 0;
    if (!init) {
        cudaFuncSetAttribute(gemm_f16,
                             cudaFuncAttributeMaxDynamicSharedMemorySize, 98304);
        cudaFuncSetAttribute(flash_f16,
                             cudaFuncAttributeMaxDynamicSharedMemorySize, 61440);
        init = 1;
    }

    preround<<<2048, 256>>>(x, Wq, Wk, Wv, Wo, Xd, Wd);

    __half* Wqh = Wd;
    __half* Wkh = Wd + 1048576;
    __half* Wvh = Wd + 2097152;
    __half* Woh = Wd + 3145728;

    dim3 qkv_grid(D_MODEL / 128, MTOT / 128, 3);  // (8, 32, 3)
    gemm_f16<<<qkv_grid, 256, 98304>>>(Xd, Wqh, Wkh, Wvh, bq, bk, bv,
                                       Qd, Kd, VTd, 1, 2, 3);

    dim3 attn_grid(SEQ / 128, BATCH * NUM_HEAD);  // (16, 32)
    flash_f16<<<attn_grid, 256, 61440>>>(Qd, Kd, VTd, Od);

    dim3 o_grid(D_MODEL / 128, MTOT / 128, 1);    // (8, 32, 1)
    gemm_f16<<<o_grid, 256, 98304>>>(Od, Woh, Woh, Woh, bo, bo, bo,
                                     out, out, out, 0, 0, 0);
}

// round 13
// speedup vs baseline: 1.8139x; 1.0414x over previous
#include <cuda_runtime.h>
#include <cuda_fp16.h>
#include <stdint.h>

#define D_MODEL 1024
#define NUM_HEAD 16
#define HEAD_DIM 64
#define BATCH 2
#define SEQ 2048
#define MTOT 4096

// fp16 scratch
__device__ __half g_Q[(size_t)MTOT * D_MODEL];
__device__ __half g_K[(size_t)MTOT * D_MODEL];
__device__ __half g_VT[(size_t)BATCH * D_MODEL * SEQ];  // [b][d_global][token]
__device__ __half g_O[(size_t)MTOT * D_MODEL];
__device__ __half g_X[(size_t)MTOT * D_MODEL];
__device__ __half g_W[(size_t)4 * D_MODEL * D_MODEL];

__device__ __forceinline__ float ex2(float x) {
    float y;
    asm("ex2.approx.ftz.f32 %0, %1;" : "=f"(y) : "f"(x));
    return y;
}
__device__ __forceinline__ uint32_t ex2_h2(uint32_t x) {
    uint32_t y;
    asm("ex2.approx.f16x2 %0, %1;" : "=r"(y) : "r"(x));
    return y;
}

__device__ __forceinline__ void mma_f16(float d[4], const uint32_t a[4],
                                        const uint32_t b[2], const float c[4]) {
    asm volatile(
        "mma.sync.aligned.m16n8k16.row.col.f32.f16.f16.f32 "
        "{%0,%1,%2,%3}, {%4,%5,%6,%7}, {%8,%9}, {%10,%11,%12,%13};\n"
        : "=f"(d[0]), "=f"(d[1]), "=f"(d[2]), "=f"(d[3])
        : "r"(a[0]), "r"(a[1]), "r"(a[2]), "r"(a[3]),
          "r"(b[0]), "r"(b[1]),
          "f"(c[0]), "f"(c[1]), "f"(c[2]), "f"(c[3]));
}

#define LDSMX4(R0, R1, R2, R3, ADDR)                                           \
    asm volatile("ldmatrix.sync.aligned.m8n8.x4.shared.b16 {%0,%1,%2,%3}, [%4];" \
                 : "=r"(R0), "=r"(R1), "=r"(R2), "=r"(R3) : "r"(ADDR))

__device__ __forceinline__ uint32_t s2u(const void* p) {
    return (uint32_t)__cvta_generic_to_shared(p);
}
__device__ __forceinline__ void cp16(uint32_t s, const void* g) {
    asm volatile("cp.async.cg.shared.global [%0], [%1], 16;" :: "r"(s), "l"(g));
}
__device__ __forceinline__ void cpcommit() {
    asm volatile("cp.async.commit_group;");
}
template <int N> __device__ __forceinline__ void cpwait() {
    asm volatile("cp.async.wait_group %0;" :: "n"(N));
}

// ---------------------------------------------------------------------------
__global__ __launch_bounds__(256) void preround(
    const float* __restrict__ x,
    const float* __restrict__ Wq, const float* __restrict__ Wk,
    const float* __restrict__ Wv, const float* __restrict__ Wo,
    __half* __restrict__ Xh, __half* __restrict__ Wh)
{
    const int bid = blockIdx.x;
    const float* src;
    __half* dst;
    size_t off;
    if (bid < 1024) {
        src = x; dst = Xh; off = (size_t)bid * 4096;
    } else {
        const int w = (bid - 1024) >> 8;
        const int lb = (bid - 1024) & 255;
        src = (w == 0) ? Wq : (w == 1) ? Wk : (w == 2) ? Wv : Wo;
        dst = Wh + (size_t)w * 1048576;
        off = (size_t)lb * 4096;
    }
    const float4* s4 = (const float4*)(src + off);
    __half2* d2 = (__half2*)(dst + off);
#pragma unroll
    for (int j = 0; j < 4; j++) {
        const int idx = threadIdx.x + j * 256;
        float4 v = s4[idx];
        d2[idx * 2] = __floats2half2_rn(v.x, v.y);
        d2[idx * 2 + 1] = __floats2half2_rn(v.z, v.w);
    }
}

// ---------------------------------------------------------------------------
// fp16 GEMM (NT): 128x128x32 tiles, 4-stage cp.async, immediate addressing.
// Smem rows stride 40 halfs (80 B): LDSM 8-row offsets {0,80,32,112,64,16,
// 96,48} mod 128 -> conflict-free. Fragments via ldmatrix.x4 (std layout).
// ---------------------------------------------------------------------------
#define GROWH 40
#define GTH (128 * GROWH)    // 5120 halfs per operand tile
#define GSTGH (2 * GTH)      // 10240 halfs per stage
#define GSTGB (GSTGH * 2)    // 20480 bytes per stage

__global__ __launch_bounds__(256) void gemm_f16(
    const __half* __restrict__ A,
    const __half* __restrict__ W0, const __half* __restrict__ W1,
    const __half* __restrict__ W2,
    const float* __restrict__ b0p, const float* __restrict__ b1p,
    const float* __restrict__ b2p,
    void* __restrict__ C0, void* __restrict__ C1, void* __restrict__ C2,
    int m0_, int m1_, int m2_)
{
    extern __shared__ __half smh[];
    const int z = blockIdx.z;
    const __half* W = (z == 0) ? W0 : (z == 1) ? W1 : W2;
    const float* bias = (z == 0) ? b0p : (z == 1) ? b1p : b2p;
    void* C = (z == 0) ? C0 : (z == 1) ? C1 : C2;
    const int mode = (z == 0) ? m0_ : (z == 1) ? m1_ : m2_;
    const float oscale = (mode == 1) ? 0.18033688011112042f : 1.0f;

    const int tid = threadIdx.x;
    const int warp = tid >> 5, lane = tid & 31;
    const int wm = warp >> 1, wn = warp & 1;
    const int tm = lane >> 2, tk = lane & 3;
    const int grp = lane >> 3, r8 = lane & 7;

    const __half* Ab = A + (size_t)(blockIdx.y * 128) * D_MODEL;
    const __half* Wb = W + (size_t)(blockIdx.x * 128) * D_MODEL;

    const int lr = tid >> 1;         // 0..127
    const int lkh = (tid & 1) * 16;  // half offset 0 or 16

    const uint32_t sAb = s2u(smh + lr * GROWH + lkh);
    const uint32_t sBb = sAb + GTH * 2;
    const __half* gA = Ab + (size_t)lr * D_MODEL + lkh;
    const __half* gW = Wb + (size_t)lr * D_MODEL + lkh;

    // LDSM lane bases (bytes): A mats {m-lo,k-lo},{m-hi,k-lo},{m-lo,k-hi},{m-hi,k-hi}
    const uint32_t aoff = ((((grp & 1) * 8 + r8) * GROWH) + (grp >> 1) * 8) * 2;
    // B mats {n-lo,k-lo},{n-lo,k-hi},{n-hi,k-lo},{n-hi,k-hi}
    const uint32_t boff = ((((grp >> 1) * 8 + r8) * GROWH) + (grp & 1) * 8) * 2;
    const uint32_t aBase = s2u(smh) + (wm * 32) * GROWH * 2 + aoff;
    const uint32_t bBase = s2u(smh) + GTH * 2 + (wn * 64) * GROWH * 2 + boff;

    float acc[2][8][4];
#pragma unroll
    for (int mt = 0; mt < 2; mt++)
#pragma unroll
        for (int nt = 0; nt < 8; nt++)
#pragma unroll
            for (int i = 0; i < 4; i++) acc[mt][nt][i] = 0.0f;

#pragma unroll
    for (int s = 0; s < 3; s++) {
        cp16(sAb + s * GSTGB, gA + s * 32);
        cp16(sAb + s * GSTGB + 16, gA + s * 32 + 8);
        cp16(sBb + s * GSTGB, gW + s * 32);
        cp16(sBb + s * GSTGB + 16, gW + s * 32 + 8);
        cpcommit();
    }

#define GEMM_STAGE(SBUF, LBUF, KO, DOLOAD)                                    \
    {                                                                          \
        cpwait<2>();                                                           \
        __syncthreads();                                                       \
        if (DOLOAD) {                                                          \
            cp16(sAb + (LBUF) * GSTGB, gA + (KO));                             \
            cp16(sAb + (LBUF) * GSTGB + 16, gA + (KO) + 8);                    \
            cp16(sBb + (LBUF) * GSTGB, gW + (KO));                             \
            cp16(sBb + (LBUF) * GSTGB + 16, gW + (KO) + 8);                    \
        }                                                                      \
        cpcommit();                                                            \
        const uint32_t sa_ = aBase + (SBUF) * GSTGB;                           \
        const uint32_t sb_ = bBase + (SBUF) * GSTGB;                           \
        _Pragma("unroll")                                                      \
        for (int ks = 0; ks < 2; ks++) {                                       \
            uint32_t af[2][4], bf[8][2];                                       \
            _Pragma("unroll")                                                  \
            for (int mt = 0; mt < 2; mt++)                                     \
                LDSMX4(af[mt][0], af[mt][1], af[mt][2], af[mt][3],             \
                       sa_ + mt * (16 * GROWH * 2) + ks * 32);                 \
            _Pragma("unroll")                                                  \
            for (int np = 0; np < 4; np++)                                     \
                LDSMX4(bf[2 * np][0], bf[2 * np][1],                           \
                       bf[2 * np + 1][0], bf[2 * np + 1][1],                   \
                       sb_ + np * (16 * GROWH * 2) + ks * 32);                 \
            _Pragma("unroll")                                                  \
            for (int mt = 0; mt < 2; mt++)                                     \
                _Pragma("unroll")                                              \
                for (int nt = 0; nt < 8; nt++)                                 \
                    mma_f16(acc[mt][nt], af[mt], bf[nt], acc[mt][nt]);         \
        }                                                                      \
    }

    int koc = 96;  // stage 3 * 32 halfs
    for (int c = 0; c < 7; c++) {
        GEMM_STAGE(0, 3, koc, 1)
        GEMM_STAGE(1, 0, koc + 32, 1)
        GEMM_STAGE(2, 1, koc + 64, 1)
        GEMM_STAGE(3, 2, koc + 96, 1)
        koc += 128;
    }
    GEMM_STAGE(0, 3, koc, 1)
    GEMM_STAGE(1, 0, 0, 0)
    GEMM_STAGE(2, 0, 0, 0)
    GEMM_STAGE(3, 0, 0, 0)
#undef GEMM_STAGE

    // ---- epilogue ----
#pragma unroll
    for (int mt = 0; mt < 2; mt++) {
        const int r0 = blockIdx.y * 128 + wm * 32 + mt * 16 + tm;
#pragma unroll
        for (int nt = 0; nt < 8; nt++) {
            const int col = blockIdx.x * 128 + wn * 64 + nt * 8 + 2 * tk;
            const float bb0 = bias[col], bb1 = bias[col + 1];
            float v0 = (acc[mt][nt][0] + bb0) * oscale;
            float v1 = (acc[mt][nt][1] + bb1) * oscale;
            float v2 = (acc[mt][nt][2] + bb0) * oscale;
            float v3 = (acc[mt][nt][3] + bb1) * oscale;
            if (mode == 0) {
                float* Cf = (float*)C;
                *(float2*)(Cf + (size_t)r0 * D_MODEL + col) = make_float2(v0, v1);
                *(float2*)(Cf + (size_t)(r0 + 8) * D_MODEL + col) =
                    make_float2(v2, v3);
            } else if (mode != 3) {
                __half* Ch = (__half*)C;
                *(__half2*)(Ch + (size_t)r0 * D_MODEL + col) =
                    __floats2half2_rn(v0, v1);
                *(__half2*)(Ch + (size_t)(r0 + 8) * D_MODEL + col) =
                    __floats2half2_rn(v2, v3);
            } else {
                const int bb = r0 >> 11;
                const int tok = r0 & 2047;
                __half* vb = (__half*)C + ((size_t)(bb * 1024 + col)) * 2048 + tok;
                vb[0] = __float2half_rn(v0);
                vb[2048] = __float2half_rn(v1);
                vb[8] = __float2half_rn(v2);
                vb[2048 + 8] = __float2half_rn(v3);
            }
        }
    }
}

// ---------------------------------------------------------------------------
// fp16 flash attention: 8 warps, BQ=128, BKT=64, split-group cp.async K/VT.
// Smem rows stride 72 halfs (144 B): LDSM 8-row offsets 16r mod 128 distinct.
// All fragments via ldmatrix.x4 (standard layouts). f16x2 exp softmax.
// Smem halfs: Qs[128*72] Ps[128*72] Ks[64*72] Vt[64*72] = 55296 B.
// ---------------------------------------------------------------------------
#define SF 72

__global__ __launch_bounds__(256, 2) void flash_f16(
    const __half* __restrict__ Qg, const __half* __restrict__ Kg,
    const __half* __restrict__ VTg, __half* __restrict__ Og)
{
    extern __shared__ __half smh[];
    __half* Qs = smh;                 // 128*72
    __half* Ps = smh + 128 * SF;      // 9216
    __half* Ks = smh + 2 * 128 * SF;  // 18432
    __half* Vt = Ks + 64 * SF;        // 23040

    const int tid = threadIdx.x;
    const int warp = tid >> 5, lane = tid & 31;
    const int tm = lane >> 2, tk = lane & 3;
    const int grp = lane >> 3, r8 = lane & 7;
    const int b = blockIdx.y >> 4, h = blockIdx.y & 15;
    const int q0 = blockIdx.x * 128;

    const __half* Qb = Qg + (size_t)(b * SEQ + q0) * D_MODEL + h * HEAD_DIM;
    const __half* Kb = Kg + (size_t)(b * SEQ) * D_MODEL + h * HEAD_DIM;

    // ---- Q tile via cp.async (group 1) ----
    {
        const int qr = tid >> 1;
        const int qc = (tid & 1) * 32;
        uint32_t sq = s2u(Qs + qr * SF + qc);
        const __half* gq = Qb + (size_t)qr * D_MODEL + qc;
        cp16(sq, gq); cp16(sq + 16, gq + 8);
        cp16(sq + 32, gq + 16); cp16(sq + 48, gq + 24);
        cpcommit();
    }

    // ---- K/VT loaders ----
    const int kr = tid >> 2;
    const int kc = (tid & 3) * 16;
    const uint32_t sK = s2u(Ks + kr * SF + kc);
    const uint32_t sV = s2u(Vt + kr * SF + kc);
    const __half* gK = Kb + (size_t)kr * D_MODEL + kc;
    const __half* gV = VTg + ((size_t)(b * 1024 + h * HEAD_DIM + kr)) * 2048 + kc;

    cp16(sK, gK); cp16(sK + 16, gK + 8);
    cpcommit();
    cp16(sV, gV); cp16(sV + 16, gV + 8);
    cpcommit();
    gK += 64 * D_MODEL;
    gV += 64;

    // ---- LDSM lane bases (bytes) ----
    const uint32_t aoff = ((((grp & 1) * 8 + r8) * SF) + (grp >> 1) * 8) * 2;
    const uint32_t boff = ((((grp >> 1) * 8 + r8) * SF) + (grp & 1) * 8) * 2;
    const uint32_t aQ = s2u(Qs + warp * 16 * SF) + aoff;
    const uint32_t aP = s2u(Ps + warp * 16 * SF) + aoff;
    const uint32_t bK = s2u(Ks) + boff;
    const uint32_t bV = s2u(Vt) + boff;

    __half* pPst = Ps + (warp * 16 + tm) * SF + 2 * tk;

    float s[8][4], acc[8][4], mi[2], li[2];
#pragma unroll
    for (int nt = 0; nt < 8; nt++)
#pragma unroll
        for (int i = 0; i < 4; i++) acc[nt][i] = 0.0f;
    mi[0] = mi[1] = -1e30f;
    li[0] = li[1] = 0.0f;

    const int NKT = SEQ / 64;  // 32

    for (int it = 0; it < NKT; it++) {
        cpwait<1>();
        __syncthreads();

        // ---- S = Q @ K^T ----
#pragma unroll
        for (int nt = 0; nt < 8; nt++)
#pragma unroll
            for (int i = 0; i < 4; i++) s[nt][i] = 0.0f;

#pragma unroll
        for (int ks = 0; ks < 4; ks++) {
            uint32_t af[4], bf[8][2];
            LDSMX4(af[0], af[1], af[2], af[3], aQ + ks * 32);
#pragma unroll
            for (int np = 0; np < 4; np++)
                LDSMX4(bf[2 * np][0], bf[2 * np][1],
                       bf[2 * np + 1][0], bf[2 * np + 1][1],
                       bK + np * (16 * SF * 2) + ks * 32);
#pragma unroll
            for (int nt = 0; nt < 8; nt++)
                mma_f16(s[nt], af, bf[nt], s[nt]);
        }

        __syncthreads();
        if (it + 1 < NKT) {
            cp16(sK, gK); cp16(sK + 16, gK + 8);
        }
        cpcommit();
        gK += 64 * D_MODEL;

        // ---- online softmax (log2 domain; f16x2 exp; P stored fp16) ----
#pragma unroll
        for (int rh = 0; rh < 2; rh++) {
            float mx = -1e30f;
#pragma unroll
            for (int nt = 0; nt < 8; nt++)
#pragma unroll
                for (int j = 0; j < 2; j++)
                    mx = fmaxf(mx, s[nt][rh * 2 + j]);
            mx = fmaxf(mx, __shfl_xor_sync(0xffffffffu, mx, 1));
            mx = fmaxf(mx, __shfl_xor_sync(0xffffffffu, mx, 2));
            const float mn = fmaxf(mi[rh], mx);
            const float corr = ex2(mi[rh] - mn);
            mi[rh] = mn;
            float sum = 0.0f;
#pragma unroll
            for (int nt = 0; nt < 8; nt++) {
                __half2 t = __floats2half2_rn(s[nt][rh * 2] - mn,
                                              s[nt][rh * 2 + 1] - mn);
                uint32_t p2 = ex2_h2(*(uint32_t*)&t);
                *(uint32_t*)(pPst + rh * (8 * SF) + nt * 8) = p2;
                __half2 ph = *(__half2*)&p2;
                sum += __low2float(ph) + __high2float(ph);
            }
            sum += __shfl_xor_sync(0xffffffffu, sum, 1);
            sum += __shfl_xor_sync(0xffffffffu, sum, 2);
            li[rh] = li[rh] * corr + sum;
#pragma unroll
            for (int nt = 0; nt < 8; nt++)
#pragma unroll
                for (int j = 0; j < 2; j++)
                    acc[nt][rh * 2 + j] *= corr;
        }
        __syncwarp();

        cpwait<1>();
        __syncthreads();

        // ---- O += P @ V ----
#pragma unroll
        for (int ks = 0; ks < 4; ks++) {
            uint32_t af[4], bf[8][2];
            LDSMX4(af[0], af[1], af[2], af[3], aP + ks * 32);
#pragma unroll
            for (int np = 0; np < 4; np++)
                LDSMX4(bf[2 * np][0], bf[2 * np][1],
                       bf[2 * np + 1][0], bf[2 * np + 1][1],
                       bV + np * (16 * SF * 2) + ks * 32);
#pragma unroll
            for (int nt = 0; nt < 8; nt++)
                mma_f16(acc[nt], af, bf[nt], acc[nt]);
        }

        __syncthreads();
        if (it + 1 < NKT) {
            cp16(sV, gV); cp16(sV + 16, gV + 8);
        }
        cpcommit();
        gV += 64;
    }

    // ---- epilogue ----
#pragma unroll
    for (int rh = 0; rh < 2; rh++) {
        const float inv = 1.0f / li[rh];
        const int row = q0 + warp * 16 + tm + rh * 8;
        __half* orow = Og + (size_t)(b * SEQ + row) * D_MODEL + h * HEAD_DIM;
#pragma unroll
        for (int nt = 0; nt < 8; nt++) {
            const int col = nt * 8 + 2 * tk;
            *(__half2*)(orow + col) =
                __floats2half2_rn(acc[nt][rh * 2] * inv, acc[nt][rh * 2 + 1] * inv);
        }
    }
}

// ---------------------------------------------------------------------------
extern "C" void kernel_launch(void* const* d_in, const int* in_sizes, int n_in,
                              void* d_out, int out_size)
{
    const float* x  = (const float*)d_in[0];
    const float* Wq = (const float*)d_in[1];
    const float* bq = (const float*)d_in[2];
    const float* Wk = (const float*)d_in[3];
    const float* bk = (const float*)d_in[4];
    const float* Wv = (const float*)d_in[5];
    const float* bv = (const float*)d_in[6];
    const float* Wo = (const float*)d_in[7];
    const float* bo = (const float*)d_in[8];
    float* out = (float*)d_out;

    __half *Qd, *Kd, *VTd, *Od, *Xd, *Wd;
    cudaGetSymbolAddress((void**)&Qd, g_Q);
    cudaGetSymbolAddress((void**)&Kd, g_K);
    cudaGetSymbolAddress((void**)&VTd, g_VT);
    cudaGetSymbolAddress((void**)&Od, g_O);
    cudaGetSymbolAddress((void**)&Xd, g_X);
    cudaGetSymbolAddress((void**)&Wd, g_W);

    static int init = 0;
    if (!init) {
        cudaFuncSetAttribute(gemm_f16,
                             cudaFuncAttributeMaxDynamicSharedMemorySize, 81920);
        cudaFuncSetAttribute(flash_f16,
                             cudaFuncAttributeMaxDynamicSharedMemorySize, 55296);
        init = 1;
    }

    preround<<<2048, 256>>>(x, Wq, Wk, Wv, Wo, Xd, Wd);

    __half* Wqh = Wd;
    __half* Wkh = Wd + 1048576;
    __half* Wvh = Wd + 2097152;
    __half* Woh = Wd + 3145728;

    dim3 qkv_grid(D_MODEL / 128, MTOT / 128, 3);  // (8, 32, 3)
    gemm_f16<<<qkv_grid, 256, 81920>>>(Xd, Wqh, Wkh, Wvh, bq, bk, bv,
                                       Qd, Kd, VTd, 1, 2, 3);

    dim3 attn_grid(SEQ / 128, BATCH * NUM_HEAD);  // (16, 32)
    flash_f16<<<attn_grid, 256, 55296>>>(Qd, Kd, VTd, Od);

    dim3 o_grid(D_MODEL / 128, MTOT / 128, 1);    // (8, 32, 1)
    gemm_f16<<<o_grid, 256, 81920>>>(Od, Woh, Woh, Woh, bo, bo, bo,
                                     out, out, out, 0, 0, 0);
}

// round 14
// speedup vs baseline: 1.9251x; 1.0613x over previous
#include <cuda_runtime.h>
#include <cuda_fp16.h>
#include <stdint.h>

#define D_MODEL 1024
#define NUM_HEAD 16
#define HEAD_DIM 64
#define BATCH 2
#define SEQ 2048
#define MTOT 4096

// fp16 scratch
__device__ __half g_Q[(size_t)MTOT * D_MODEL];
__device__ __half g_K[(size_t)MTOT * D_MODEL];
__device__ __half g_VT[(size_t)BATCH * D_MODEL * SEQ];  // [b][d_global][token]
__device__ __half g_O[(size_t)MTOT * D_MODEL];
__device__ __half g_X[(size_t)MTOT * D_MODEL];
__device__ __half g_W[(size_t)4 * D_MODEL * D_MODEL];

__device__ __forceinline__ float ex2(float x) {
    float y;
    asm("ex2.approx.ftz.f32 %0, %1;" : "=f"(y) : "f"(x));
    return y;
}
__device__ __forceinline__ uint32_t ex2_h2(uint32_t x) {
    uint32_t y;
    asm("ex2.approx.f16x2 %0, %1;" : "=r"(y) : "r"(x));
    return y;
}

__device__ __forceinline__ void mma_f16(float d[4], const uint32_t a[4],
                                        const uint32_t b[2], const float c[4]) {
    asm volatile(
        "mma.sync.aligned.m16n8k16.row.col.f32.f16.f16.f32 "
        "{%0,%1,%2,%3}, {%4,%5,%6,%7}, {%8,%9}, {%10,%11,%12,%13};\n"
        : "=f"(d[0]), "=f"(d[1]), "=f"(d[2]), "=f"(d[3])
        : "r"(a[0]), "r"(a[1]), "r"(a[2]), "r"(a[3]),
          "r"(b[0]), "r"(b[1]),
          "f"(c[0]), "f"(c[1]), "f"(c[2]), "f"(c[3]));
}

#define LDSMX4(R0, R1, R2, R3, ADDR)                                           \
    asm volatile("ldmatrix.sync.aligned.m8n8.x4.shared.b16 {%0,%1,%2,%3}, [%4];" \
                 : "=r"(R0), "=r"(R1), "=r"(R2), "=r"(R3) : "r"(ADDR))

__device__ __forceinline__ uint32_t s2u(const void* p) {
    return (uint32_t)__cvta_generic_to_shared(p);
}
__device__ __forceinline__ void cp16(uint32_t s, const void* g) {
    asm volatile("cp.async.cg.shared.global [%0], [%1], 16;" :: "r"(s), "l"(g));
}
__device__ __forceinline__ void cpcommit() {
    asm volatile("cp.async.commit_group;");
}
template <int N> __device__ __forceinline__ void cpwait() {
    asm volatile("cp.async.wait_group %0;" :: "n"(N));
}

// ---------------------------------------------------------------------------
__global__ __launch_bounds__(256) void preround(
    const float* __restrict__ x,
    const float* __restrict__ Wq, const float* __restrict__ Wk,
    const float* __restrict__ Wv, const float* __restrict__ Wo,
    __half* __restrict__ Xh, __half* __restrict__ Wh)
{
    const int bid = blockIdx.x;
    const float* src;
    __half* dst;
    size_t off;
    if (bid < 1024) {
        src = x; dst = Xh; off = (size_t)bid * 4096;
    } else {
        const int w = (bid - 1024) >> 8;
        const int lb = (bid - 1024) & 255;
        src = (w == 0) ? Wq : (w == 1) ? Wk : (w == 2) ? Wv : Wo;
        dst = Wh + (size_t)w * 1048576;
        off = (size_t)lb * 4096;
    }
    const float4* s4 = (const float4*)(src + off);
    __half2* d2 = (__half2*)(dst + off);
#pragma unroll
    for (int j = 0; j < 4; j++) {
        const int idx = threadIdx.x + j * 256;
        float4 v = s4[idx];
        d2[idx * 2] = __floats2half2_rn(v.x, v.y);
        d2[idx * 2 + 1] = __floats2half2_rn(v.z, v.w);
    }
}

// ---------------------------------------------------------------------------
// fp16 GEMM (NT): 128x128x32 tiles, 4-stage cp.async, immediate addressing.
// Smem rows stride 40 halfs (80 B): LDSM conflict-free. ldmatrix.x4 frags.
// __launch_bounds__(256,2) caps regs at 128 -> 2 CTAs/SM.
// ---------------------------------------------------------------------------
#define GROWH 40
#define GTH (128 * GROWH)    // 5120 halfs per operand tile
#define GSTGH (2 * GTH)      // 10240 halfs per stage
#define GSTGB (GSTGH * 2)    // 20480 bytes per stage

__global__ __launch_bounds__(256, 2) void gemm_f16(
    const __half* __restrict__ A,
    const __half* __restrict__ W0, const __half* __restrict__ W1,
    const __half* __restrict__ W2,
    const float* __restrict__ b0p, const float* __restrict__ b1p,
    const float* __restrict__ b2p,
    void* __restrict__ C0, void* __restrict__ C1, void* __restrict__ C2,
    int m0_, int m1_, int m2_)
{
    extern __shared__ __half smh[];
    const int z = blockIdx.z;
    const __half* W = (z == 0) ? W0 : (z == 1) ? W1 : W2;
    const float* bias = (z == 0) ? b0p : (z == 1) ? b1p : b2p;
    void* C = (z == 0) ? C0 : (z == 1) ? C1 : C2;
    const int mode = (z == 0) ? m0_ : (z == 1) ? m1_ : m2_;
    const float oscale = (mode == 1) ? 0.18033688011112042f : 1.0f;

    const int tid = threadIdx.x;
    const int warp = tid >> 5, lane = tid & 31;
    const int wm = warp >> 1, wn = warp & 1;
    const int tm = lane >> 2, tk = lane & 3;
    const int grp = lane >> 3, r8 = lane & 7;

    const __half* Ab = A + (size_t)(blockIdx.y * 128) * D_MODEL;
    const __half* Wb = W + (size_t)(blockIdx.x * 128) * D_MODEL;

    const int lr = tid >> 1;         // 0..127
    const int lkh = (tid & 1) * 16;  // half offset 0 or 16

    const uint32_t sAb = s2u(smh + lr * GROWH + lkh);
    const uint32_t sBb = sAb + GTH * 2;
    const __half* gA = Ab + (size_t)lr * D_MODEL + lkh;
    const __half* gW = Wb + (size_t)lr * D_MODEL + lkh;

    const uint32_t aoff = ((((grp & 1) * 8 + r8) * GROWH) + (grp >> 1) * 8) * 2;
    const uint32_t boff = ((((grp >> 1) * 8 + r8) * GROWH) + (grp & 1) * 8) * 2;
    const uint32_t aBase = s2u(smh) + (wm * 32) * GROWH * 2 + aoff;
    const uint32_t bBase = s2u(smh) + GTH * 2 + (wn * 64) * GROWH * 2 + boff;

    float acc[2][8][4];
#pragma unroll
    for (int mt = 0; mt < 2; mt++)
#pragma unroll
        for (int nt = 0; nt < 8; nt++)
#pragma unroll
            for (int i = 0; i < 4; i++) acc[mt][nt][i] = 0.0f;

#pragma unroll
    for (int s = 0; s < 3; s++) {
        cp16(sAb + s * GSTGB, gA + s * 32);
        cp16(sAb + s * GSTGB + 16, gA + s * 32 + 8);
        cp16(sBb + s * GSTGB, gW + s * 32);
        cp16(sBb + s * GSTGB + 16, gW + s * 32 + 8);
        cpcommit();
    }

#define GEMM_STAGE(SBUF, LBUF, KO, DOLOAD)                                    \
    {                                                                          \
        cpwait<2>();                                                           \
        __syncthreads();                                                       \
        if (DOLOAD) {                                                          \
            cp16(sAb + (LBUF) * GSTGB, gA + (KO));                             \
            cp16(sAb + (LBUF) * GSTGB + 16, gA + (KO) + 8);                    \
            cp16(sBb + (LBUF) * GSTGB, gW + (KO));                             \
            cp16(sBb + (LBUF) * GSTGB + 16, gW + (KO) + 8);                    \
        }                                                                      \
        cpcommit();                                                            \
        const uint32_t sa_ = aBase + (SBUF) * GSTGB;                           \
        const uint32_t sb_ = bBase + (SBUF) * GSTGB;                           \
        _Pragma("unroll")                                                      \
        for (int ks = 0; ks < 2; ks++) {                                       \
            uint32_t af[2][4], bf[8][2];                                       \
            _Pragma("unroll")                                                  \
            for (int mt = 0; mt < 2; mt++)                                     \
                LDSMX4(af[mt][0], af[mt][1], af[mt][2], af[mt][3],             \
                       sa_ + mt * (16 * GROWH * 2) + ks * 32);                 \
            _Pragma("unroll")                                                  \
            for (int np = 0; np < 4; np++)                                     \
                LDSMX4(bf[2 * np][0], bf[2 * np][1],                           \
                       bf[2 * np + 1][0], bf[2 * np + 1][1],                   \
                       sb_ + np * (16 * GROWH * 2) + ks * 32);                 \
            _Pragma("unroll")                                                  \
            for (int mt = 0; mt < 2; mt++)                                     \
                _Pragma("unroll")                                              \
                for (int nt = 0; nt < 8; nt++)                                 \
                    mma_f16(acc[mt][nt], af[mt], bf[nt], acc[mt][nt]);         \
        }                                                                      \
    }

    int koc = 96;  // stage 3 * 32 halfs
    for (int c = 0; c < 7; c++) {
        GEMM_STAGE(0, 3, koc, 1)
        GEMM_STAGE(1, 0, koc + 32, 1)
        GEMM_STAGE(2, 1, koc + 64, 1)
        GEMM_STAGE(3, 2, koc + 96, 1)
        koc += 128;
    }
    GEMM_STAGE(0, 3, koc, 1)
    GEMM_STAGE(1, 0, 0, 0)
    GEMM_STAGE(2, 0, 0, 0)
    GEMM_STAGE(3, 0, 0, 0)
#undef GEMM_STAGE

    // ---- epilogue ----
#pragma unroll
    for (int mt = 0; mt < 2; mt++) {
        const int r0 = blockIdx.y * 128 + wm * 32 + mt * 16 + tm;
#pragma unroll
        for (int nt = 0; nt < 8; nt++) {
            const int col = blockIdx.x * 128 + wn * 64 + nt * 8 + 2 * tk;
            const float bb0 = bias[col], bb1 = bias[col + 1];
            float v0 = (acc[mt][nt][0] + bb0) * oscale;
            float v1 = (acc[mt][nt][1] + bb1) * oscale;
            float v2 = (acc[mt][nt][2] + bb0) * oscale;
            float v3 = (acc[mt][nt][3] + bb1) * oscale;
            if (mode == 0) {
                float* Cf = (float*)C;
                *(float2*)(Cf + (size_t)r0 * D_MODEL + col) = make_float2(v0, v1);
                *(float2*)(Cf + (size_t)(r0 + 8) * D_MODEL + col) =
                    make_float2(v2, v3);
            } else if (mode != 3) {
                __half* Ch = (__half*)C;
                *(__half2*)(Ch + (size_t)r0 * D_MODEL + col) =
                    __floats2half2_rn(v0, v1);
                *(__half2*)(Ch + (size_t)(r0 + 8) * D_MODEL + col) =
                    __floats2half2_rn(v2, v3);
            } else {
                const int bb = r0 >> 11;
                const int tok = r0 & 2047;
                __half* vb = (__half*)C + ((size_t)(bb * 1024 + col)) * 2048 + tok;
                vb[0] = __float2half_rn(v0);
                vb[2048] = __float2half_rn(v1);
                vb[8] = __float2half_rn(v2);
                vb[2048 + 8] = __float2half_rn(v3);
            }
        }
    }
}

// ---------------------------------------------------------------------------
// fp16 flash attention: 8 warps, BQ=128, BKT=64, split-group cp.async K/VT.
// Smem rows stride 72 halfs (144 B). ldmatrix.x4 frags, f16x2 exp softmax.
// Smem halfs: Qs[128*72] Ps[128*72] Ks[64*72] Vt[64*72] = 55296 B. 2 CTA/SM.
// ---------------------------------------------------------------------------
#define SF 72

__global__ __launch_bounds__(256, 2) void flash_f16(
    const __half* __restrict__ Qg, const __half* __restrict__ Kg,
    const __half* __restrict__ VTg, __half* __restrict__ Og)
{
    extern __shared__ __half smh[];
    __half* Qs = smh;                 // 128*72
    __half* Ps = smh + 128 * SF;
    __half* Ks = smh + 2 * 128 * SF;
    __half* Vt = Ks + 64 * SF;

    const int tid = threadIdx.x;
    const int warp = tid >> 5, lane = tid & 31;
    const int tm = lane >> 2, tk = lane & 3;
    const int grp = lane >> 3, r8 = lane & 7;
    const int b = blockIdx.y >> 4, h = blockIdx.y & 15;
    const int q0 = blockIdx.x * 128;

    const __half* Qb = Qg + (size_t)(b * SEQ + q0) * D_MODEL + h * HEAD_DIM;
    const __half* Kb = Kg + (size_t)(b * SEQ) * D_MODEL + h * HEAD_DIM;

    // ---- Q tile via cp.async (group 1) ----
    {
        const int qr = tid >> 1;
        const int qc = (tid & 1) * 32;
        uint32_t sq = s2u(Qs + qr * SF + qc);
        const __half* gq = Qb + (size_t)qr * D_MODEL + qc;
        cp16(sq, gq); cp16(sq + 16, gq + 8);
        cp16(sq + 32, gq + 16); cp16(sq + 48, gq + 24);
        cpcommit();
    }

    // ---- K/VT loaders ----
    const int kr = tid >> 2;
    const int kc = (tid & 3) * 16;
    const uint32_t sK = s2u(Ks + kr * SF + kc);
    const uint32_t sV = s2u(Vt + kr * SF + kc);
    const __half* gK = Kb + (size_t)kr * D_MODEL + kc;
    const __half* gV = VTg + ((size_t)(b * 1024 + h * HEAD_DIM + kr)) * 2048 + kc;

    cp16(sK, gK); cp16(sK + 16, gK + 8);
    cpcommit();
    cp16(sV, gV); cp16(sV + 16, gV + 8);
    cpcommit();
    gK += 64 * D_MODEL;
    gV += 64;

    // ---- LDSM lane bases (bytes) ----
    const uint32_t aoff = ((((grp & 1) * 8 + r8) * SF) + (grp >> 1) * 8) * 2;
    const uint32_t boff = ((((grp >> 1) * 8 + r8) * SF) + (grp & 1) * 8) * 2;
    const uint32_t aQ = s2u(Qs + warp * 16 * SF) + aoff;
    const uint32_t aP = s2u(Ps + warp * 16 * SF) + aoff;
    const uint32_t bK = s2u(Ks) + boff;
    const uint32_t bV = s2u(Vt) + boff;

    __half* pPst = Ps + (warp * 16 + tm) * SF + 2 * tk;

    float s[8][4], acc[8][4], mi[2], li[2];
#pragma unroll
    for (int nt = 0; nt < 8; nt++)
#pragma unroll
        for (int i = 0; i < 4; i++) acc[nt][i] = 0.0f;
    mi[0] = mi[1] = -1e30f;
    li[0] = li[1] = 0.0f;

    const int NKT = SEQ / 64;  // 32

    for (int it = 0; it < NKT; it++) {
        cpwait<1>();
        __syncthreads();

        // ---- S = Q @ K^T ----
#pragma unroll
        for (int nt = 0; nt < 8; nt++)
#pragma unroll
            for (int i = 0; i < 4; i++) s[nt][i] = 0.0f;

#pragma unroll
        for (int ks = 0; ks < 4; ks++) {
            uint32_t af[4], bf[8][2];
            LDSMX4(af[0], af[1], af[2], af[3], aQ + ks * 32);
#pragma unroll
            for (int np = 0; np < 4; np++)
                LDSMX4(bf[2 * np][0], bf[2 * np][1],
                       bf[2 * np + 1][0], bf[2 * np + 1][1],
                       bK + np * (16 * SF * 2) + ks * 32);
#pragma unroll
            for (int nt = 0; nt < 8; nt++)
                mma_f16(s[nt], af, bf[nt], s[nt]);
        }

        __syncthreads();
        if (it + 1 < NKT) {
            cp16(sK, gK); cp16(sK + 16, gK + 8);
        }
        cpcommit();
        gK += 64 * D_MODEL;

        // ---- online softmax (log2 domain; f16x2 exp; P stored fp16) ----
#pragma unroll
        for (int rh = 0; rh < 2; rh++) {
            float mx = -1e30f;
#pragma unroll
            for (int nt = 0; nt < 8; nt++)
#pragma unroll
                for (int j = 0; j < 2; j++)
                    mx = fmaxf(mx, s[nt][rh * 2 + j]);
            mx = fmaxf(mx, __shfl_xor_sync(0xffffffffu, mx, 1));
            mx = fmaxf(mx, __shfl_xor_sync(0xffffffffu, mx, 2));
            const float mn = fmaxf(mi[rh], mx);
            const float corr = ex2(mi[rh] - mn);
            mi[rh] = mn;
            float sum = 0.0f;
#pragma unroll
            for (int nt = 0; nt < 8; nt++) {
                __half2 t = __floats2half2_rn(s[nt][rh * 2] - mn,
                                              s[nt][rh * 2 + 1] - mn);
                uint32_t p2 = ex2_h2(*(uint32_t*)&t);
                *(uint32_t*)(pPst + rh * (8 * SF) + nt * 8) = p2;
                __half2 ph = *(__half2*)&p2;
                sum += __low2float(ph) + __high2float(ph);
            }
            sum += __shfl_xor_sync(0xffffffffu, sum, 1);
            sum += __shfl_xor_sync(0xffffffffu, sum, 2);
            li[rh] = li[rh] * corr + sum;
#pragma unroll
            for (int nt = 0; nt < 8; nt++)
#pragma unroll
                for (int j = 0; j < 2; j++)
                    acc[nt][rh * 2 + j] *= corr;
        }
        __syncwarp();

        cpwait<1>();
        __syncthreads();

        // ---- O += P @ V ----
#pragma unroll
        for (int ks = 0; ks < 4; ks++) {
            uint32_t af[4], bf[8][2];
            LDSMX4(af[0], af[1], af[2], af[3], aP + ks * 32);
#pragma unroll
            for (int np = 0; np < 4; np++)
                LDSMX4(bf[2 * np][0], bf[2 * np][1],
                       bf[2 * np + 1][0], bf[2 * np + 1][1],
                       bV + np * (16 * SF * 2) + ks * 32);
#pragma unroll
            for (int nt = 0; nt < 8; nt++)
                mma_f16(acc[nt], af, bf[nt], acc[nt]);
        }

        __syncthreads();
        if (it + 1 < NKT) {
            cp16(sV, gV); cp16(sV + 16, gV + 8);
        }
        cpcommit();
        gV += 64;
    }

    // ---- epilogue ----
#pragma unroll
    for (int rh = 0; rh < 2; rh++) {
        const float inv = 1.0f / li[rh];
        const int row = q0 + warp * 16 + tm + rh * 8;
        __half* orow = Og + (size_t)(b * SEQ + row) * D_MODEL + h * HEAD_DIM;
#pragma unroll
        for (int nt = 0; nt < 8; nt++) {
            const int col = nt * 8 + 2 * tk;
            *(__half2*)(orow + col) =
                __floats2half2_rn(acc[nt][rh * 2] * inv, acc[nt][rh * 2 + 1] * inv);
        }
    }
}

// ---------------------------------------------------------------------------
extern "C" void kernel_launch(void* const* d_in, const int* in_sizes, int n_in,
                              void* d_out, int out_size)
{
    const float* x  = (const float*)d_in[0];
    const float* Wq = (const float*)d_in[1];
    const float* bq = (const float*)d_in[2];
    const float* Wk = (const float*)d_in[3];
    const float* bk = (const float*)d_in[4];
    const float* Wv = (const float*)d_in[5];
    const float* bv = (const float*)d_in[6];
    const float* Wo = (const float*)d_in[7];
    const float* bo = (const float*)d_in[8];
    float* out = (float*)d_out;

    __half *Qd, *Kd, *VTd, *Od, *Xd, *Wd;
    cudaGetSymbolAddress((void**)&Qd, g_Q);
    cudaGetSymbolAddress((void**)&Kd, g_K);
    cudaGetSymbolAddress((void**)&VTd, g_VT);
    cudaGetSymbolAddress((void**)&Od, g_O);
    cudaGetSymbolAddress((void**)&Xd, g_X);
    cudaGetSymbolAddress((void**)&Wd, g_W);

    static int init = 0;
    if (!init) {
        cudaFuncSetAttribute(gemm_f16,
                             cudaFuncAttributeMaxDynamicSharedMemorySize, 81920);
        cudaFuncSetAttribute(flash_f16,
                             cudaFuncAttributeMaxDynamicSharedMemorySize, 55296);
        init = 1;
    }

    preround<<<2048, 256>>>(x, Wq, Wk, Wv, Wo, Xd, Wd);

    __half* Wqh = Wd;
    __half* Wkh = Wd + 1048576;
    __half* Wvh = Wd + 2097152;
    __half* Woh = Wd + 3145728;

    dim3 qkv_grid(D_MODEL / 128, MTOT / 128, 3);  // (8, 32, 3)
    gemm_f16<<<qkv_grid, 256, 81920>>>(Xd, Wqh, Wkh, Wvh, bq, bk, bv,
                                       Qd, Kd, VTd, 1, 2, 3);

    dim3 attn_grid(SEQ / 128, BATCH * NUM_HEAD);  // (16, 32)
    flash_f16<<<attn_grid, 256, 55296>>>(Qd, Kd, VTd, Od);

    dim3 o_grid(D_MODEL / 128, MTOT / 128, 1);    // (8, 32, 1)
    gemm_f16<<<o_grid, 256, 81920>>>(Od, Woh, Woh, Woh, bo, bo, bo,
                                     out, out, out, 0, 0, 0);
}